// round 12
// baseline (speedup 1.0000x reference)
#include <cuda_runtime.h>
#include <cuda_fp16.h>
#include <stdint.h>

// ---------------- problem constants ----------------
#define PN      576
#define B0c     64
#define BTOT    128
#define CIN     256
#define CH      256
#define NNODES  36864
#define KNN     9

// ---------------- scratch (device globals) ----------------
__device__ __align__(16) __half g_h  [NNODES * CH];   // fp16 storage
__device__ float g_as [NNODES * 2];
__device__ float g_ad [NNODES * 2];
__device__ __align__(16) float g_alpha[NNODES * 20];  // [d][head][10]
__device__ float g_w  [NNODES * 2];                   // per-source summed alpha
__device__ __align__(16) float g_emb [B0c * CH];
__device__ __align__(16) float g_h2  [BTOT * CH];
__device__ float g_as2[BTOT];
__device__ float g_ad2[BTOT];
__device__ __align__(16) float g_feat[BTOT * CH];
__device__ int   g_m64s;
__device__ int   g_m64v;
// pre-converted, pre-swizzled W_space as B operand: [chunk][n=256][kk=64] fp16, SW128 rows
__device__ __align__(16) __half g_Bhi[4 * 256 * 64];
__device__ __align__(16) __half g_Blo[4 * 256 * 64];

// ---------------- helpers ----------------
__device__ __forceinline__ uint32_t smem_u32(const void* p) {
    return (uint32_t)__cvta_generic_to_shared(p);
}
__device__ __forceinline__ uint32_t sw128(uint32_t bo) { return bo ^ ((bo >> 3) & 0x70); }

__device__ __forceinline__ void cp_async16(uint32_t s, const void* g) {
    asm volatile("{\n\t.reg .u64 p;\n\tcvta.to.global.u64 p, %1;\n\t"
                 "cp.async.cg.shared.global [%0], [p], 16;\n\t}"
                 :: "r"(s), "l"(g) : "memory");
}
__device__ __forceinline__ void cp_commit() {
    asm volatile("cp.async.commit_group;" ::: "memory");
}
__device__ __forceinline__ void cp_wait0() {
    asm volatile("cp.async.wait_group 0;" ::: "memory");
}
__device__ __forceinline__ void ldmx4(uint32_t* r, uint32_t addr) {
    asm volatile("ldmatrix.sync.aligned.m8n8.x4.shared.b16 {%0,%1,%2,%3}, [%4];"
                 : "=r"(r[0]), "=r"(r[1]), "=r"(r[2]), "=r"(r[3]) : "r"(addr));
}
__device__ __forceinline__ void mma16816(float* d, const uint32_t* a,
                                         uint32_t b0, uint32_t b1) {
    asm volatile("mma.sync.aligned.m16n8k16.row.col.f32.f16.f16.f32 "
                 "{%0,%1,%2,%3}, {%4,%5,%6,%7}, {%8,%9}, {%0,%1,%2,%3};"
                 : "+f"(d[0]), "+f"(d[1]), "+f"(d[2]), "+f"(d[3])
                 : "r"(a[0]), "r"(a[1]), "r"(a[2]), "r"(a[3]), "r"(b0), "r"(b1));
}

// edge index read robust to int32/int64 storage
__device__ __forceinline__ int eread(const void* p, long long i, int m64) {
    if (m64) return (int)((const long long*)p)[i];
    return ((const int*)p)[i];
}

// ---------------- K0: dtype detection ----------------
__global__ void k_detect(const unsigned int* __restrict__ es,
                         const unsigned int* __restrict__ ev, int nv) {
    if (threadIdx.x == 0) {
        int nz = 0;
        for (int i = 0; i < 64; i++) nz += (es[2 * i + 1] != 0u);
        g_m64s = (nz == 0) ? 1 : 0;
        nz = 0;
        int m = nv < 64 ? nv : 64;
        for (int i = 0; i < m; i++) nz += (ev[2 * i + 1] != 0u);
        g_m64v = (nz == 0) ? 1 : 0;
    }
}

// ---------------- K1: prep W (swizzled fp16 hi/lo) + zero emb/w ----------------
__global__ void __launch_bounds__(256) k_prep(const float* __restrict__ W) {
    int idx = blockIdx.x * 256 + threadIdx.x;   // 0..73727
    if (idx < B0c * CH) g_emb[idx] = 0.f;
    if (idx < NNODES * 2) g_w[idx] = 0.f;
    if (idx < 65536) {
        int chunk = idx >> 14;
        int r = idx & 16383;
        int n = r >> 6;
        int kk = r & 63;
        int c = chunk * 64 + kk;
        float v = W[c * 256 + n];
        __half hi = __float2half(v);
        __half lo = __float2half(v - __half2float(hi));
        uint32_t sw = sw128((uint32_t)n * 128 + kk * 2);
        *(__half*)((char*)g_Bhi + chunk * 32768 + sw) = hi;
        *(__half*)((char*)g_Blo + chunk * 32768 + sw) = lo;
    }
}

// ---------------- K2: 2-term fp16 mma.sync GEMM + fused attention logits ----------
#define BUFSZ    81920
#define OFF_BHI  16384
#define OFF_BLO  49152
#define OFF_VAS  (2 * BUFSZ)
#define OFF_VAD  (2 * BUFSZ + 1024)
#define OFF_PAS  (2 * BUFSZ + 2048)
#define OFF_PAD  (2 * BUFSZ + 3072)
#define SM_TOTAL (2 * BUFSZ + 4096 + 1024)

__global__ void __launch_bounds__(512)
k_gemm_mma(const float* __restrict__ x, const float* __restrict__ asrc,
           const float* __restrict__ adst) {
    extern __shared__ char dsm[];
    const uint32_t sb_raw = smem_u32(dsm);
    const uint32_t pad = ((sb_raw + 1023u) & ~1023u) - sb_raw;
    char* base = dsm + pad;
    const uint32_t sb = sb_raw + pad;

    const int tid = threadIdx.x;
    const int wid = tid >> 5, lane = tid & 31;
    float* s_vas = (float*)(base + OFF_VAS);
    float* s_vad = (float*)(base + OFF_VAD);
    float* s_pas = (float*)(base + OFF_PAS);
    float* s_pad = (float*)(base + OFF_PAD);
    if (tid < 256) {
        s_vas[tid] = asrc[tid];
        s_vad[tid] = adst[tid];
        s_pas[tid] = 0.f;
        s_pad[tid] = 0.f;
    }

    const int tile_m = blockIdx.x * 128;
    const int ml = tid & 127;
    const int q  = tid >> 7;
    const int m = tile_m + ml;
    const unsigned bimg = (unsigned)m / 576u;
    const unsigned p = (unsigned)m - bimg * 576u;
    const float* xb = x + (size_t)bimg * (CIN * PN) + p;

    // ---- prologue: chunk 0 into buf 0
    {
        const char* sH = (const char*)g_Bhi;
        const char* sL = (const char*)g_Blo;
#pragma unroll
        for (int i = 0; i < 4; i++) {
            cp_async16(sb + OFF_BHI + tid * 16 + i * 8192, sH + tid * 16 + i * 8192);
            cp_async16(sb + OFF_BLO + tid * 16 + i * 8192, sL + tid * 16 + i * 8192);
        }
        cp_commit();
        char* Ah = base;
#pragma unroll
        for (int s = 0; s < 8; s++) {
            int kp = s * 4 + q;
            float v0 = xb[(size_t)(kp * 2) * PN];
            float v1 = xb[(size_t)(kp * 2 + 1) * PN];
            __half2 hh; hh.x = __float2half(v0); hh.y = __float2half(v1);
            uint32_t sw = sw128((uint32_t)ml * 128 + kp * 4);
            *(__half2*)(Ah + sw) = hh;
        }
        cp_wait0();
    }
    __syncthreads();

    // ---- main loop
    const int wm = wid & 3, wn = wid >> 2;
    const int mi = lane >> 3, rr = lane & 7;
    float d[2][8][4];
#pragma unroll
    for (int a = 0; a < 2; a++)
#pragma unroll
        for (int b = 0; b < 8; b++)
#pragma unroll
            for (int c = 0; c < 4; c++) d[a][b][c] = 0.f;

    float va[16];
    for (int c = 0; c < 4; c++) {
        const int buf = c & 1;
        const uint32_t Ab = sb + buf * BUFSZ;
        const uint32_t Bb = Ab + OFF_BHI;

        if (c < 3) {
            const uint32_t Ab2 = sb + (buf ^ 1) * BUFSZ;
            const char* sH = (const char*)g_Bhi + (c + 1) * 32768;
            const char* sL = (const char*)g_Blo + (c + 1) * 32768;
#pragma unroll
            for (int i = 0; i < 4; i++) {
                cp_async16(Ab2 + OFF_BHI + tid * 16 + i * 8192, sH + tid * 16 + i * 8192);
                cp_async16(Ab2 + OFF_BLO + tid * 16 + i * 8192, sL + tid * 16 + i * 8192);
            }
            cp_commit();
            const float* xc = xb + (size_t)(c + 1) * 64 * PN;
#pragma unroll
            for (int s = 0; s < 8; s++) {
                int kp = s * 4 + q;
                va[s * 2]     = xc[(size_t)(kp * 2) * PN];
                va[s * 2 + 1] = xc[(size_t)(kp * 2 + 1) * PN];
            }
        }

#pragma unroll
        for (int ks = 0; ks < 4; ks++) {
            const int kb = ks * 32;
            uint32_t ah[2][4];
#pragma unroll
            for (int mt = 0; mt < 2; mt++) {
                uint32_t aoff = sw128((uint32_t)(wm * 32 + mt * 16 + (mi & 1) * 8 + rr) * 128
                                      + kb + (mi >> 1) * 16);
                ldmx4(ah[mt], Ab + aoff);
            }
#pragma unroll
            for (int bt = 0; bt < 4; bt++) {
                uint32_t boff = sw128((uint32_t)(wn * 64 + bt * 16 + (mi >> 1) * 8 + rr) * 128
                                      + kb + (mi & 1) * 16);
                uint32_t bhi[4], blo[4];
                ldmx4(bhi, Bb + boff);
                ldmx4(blo, Bb + (OFF_BLO - OFF_BHI) + boff);
#pragma unroll
                for (int mt = 0; mt < 2; mt++)
#pragma unroll
                    for (int sub = 0; sub < 2; sub++)
                        mma16816(d[mt][bt * 2 + sub], ah[mt], bhi[sub * 2], bhi[sub * 2 + 1]);
#pragma unroll
                for (int mt = 0; mt < 2; mt++)
#pragma unroll
                    for (int sub = 0; sub < 2; sub++)
                        mma16816(d[mt][bt * 2 + sub], ah[mt], blo[sub * 2], blo[sub * 2 + 1]);
            }
        }

        if (c < 3) {
            char* Ah = base + (buf ^ 1) * BUFSZ;
#pragma unroll
            for (int s = 0; s < 8; s++) {
                int kp = s * 4 + q;
                __half2 hh; hh.x = __float2half(va[s * 2]); hh.y = __float2half(va[s * 2 + 1]);
                uint32_t sw = sw128((uint32_t)ml * 128 + kp * 4);
                *(__half2*)(Ah + sw) = hh;
            }
            cp_wait0();
            __syncthreads();
        }
    }

    // ---- epilogue: store g_h (fp16) + fused logits from fp32 accumulators
    float ps[2][2], pd[2][2];
#pragma unroll
    for (int a = 0; a < 2; a++) { ps[a][0] = ps[a][1] = pd[a][0] = pd[a][1] = 0.f; }

    const int g = lane >> 2, t4 = lane & 3;
#pragma unroll
    for (int mt = 0; mt < 2; mt++) {
        const int rg = tile_m + wm * 32 + mt * 16 + g;
#pragma unroll
        for (int bt = 0; bt < 4; bt++) {
#pragma unroll
            for (int sub = 0; sub < 2; sub++) {
                const int col = wn * 64 + bt * 16 + sub * 8 + t4 * 2;
                const float* dd = d[mt][bt * 2 + sub];
                float a0 = s_vas[col], a1 = s_vas[col + 1];
                float b0 = s_vad[col], b1 = s_vad[col + 1];
                ps[mt][0] += dd[0] * a0 + dd[1] * a1;
                pd[mt][0] += dd[0] * b0 + dd[1] * b1;
                ps[mt][1] += dd[2] * a0 + dd[3] * a1;
                pd[mt][1] += dd[2] * b0 + dd[3] * b1;
                __half2 h0; h0.x = __float2half(dd[0]); h0.y = __float2half(dd[1]);
                __half2 h1; h1.x = __float2half(dd[2]); h1.y = __float2half(dd[3]);
                *(__half2*)&g_h[(size_t)rg * CH + col]       = h0;
                *(__half2*)&g_h[(size_t)(rg + 8) * CH + col] = h1;
            }
        }
    }
#pragma unroll
    for (int mt = 0; mt < 2; mt++) {
#pragma unroll
        for (int hh = 0; hh < 2; hh++) {
            ps[mt][hh] += __shfl_xor_sync(0xffffffffu, ps[mt][hh], 1);
            ps[mt][hh] += __shfl_xor_sync(0xffffffffu, ps[mt][hh], 2);
            pd[mt][hh] += __shfl_xor_sync(0xffffffffu, pd[mt][hh], 1);
            pd[mt][hh] += __shfl_xor_sync(0xffffffffu, pd[mt][hh], 2);
        }
    }
    if (t4 == 0) {
        const int head = wn >> 1;
#pragma unroll
        for (int mt = 0; mt < 2; mt++) {
            const int rl = wm * 32 + mt * 16 + g;
            atomicAdd(&s_pas[rl * 2 + head],       ps[mt][0]);
            atomicAdd(&s_pad[rl * 2 + head],       pd[mt][0]);
            atomicAdd(&s_pas[(rl + 8) * 2 + head], ps[mt][1]);
            atomicAdd(&s_pad[(rl + 8) * 2 + head], pd[mt][1]);
        }
    }
    __syncthreads();
    if (tid < 256) {
        g_as[tile_m * 2 + tid] = s_pas[tid];
        g_ad[tile_m * 2 + tid] = s_pad[tid];
    }
}

// ---------------- K3: softmax alphas + per-source weights ----------------
// Half-warp per head, 4 dsts per warp. g_alpha[d*20 + head*10 + slot].
__global__ void __launch_bounds__(256)
k_alpha(const void* __restrict__ ei) {
    const int tid = threadIdx.x, warp = tid >> 5, lane = tid & 31;
    const int hl = lane & 15;
    const int head = lane >> 4;
    const int d0 = blockIdx.x * 32 + warp * 4;
    const int m64 = g_m64s;

#pragma unroll
    for (int r = 0; r < 4; r++) {
        const int d = d0 + r;
        int s = d;
        if (hl < 9) s = eread(ei, (long long)d * KNN + hl, m64);

        float e = -1e30f;
        if (hl < 10) {
            e = g_as[s * 2 + head] + g_ad[d * 2 + head];
            e = e > 0.f ? e : 0.2f * e;
        }
        float mx = e;
#pragma unroll
        for (int o = 8; o; o >>= 1)
            mx = fmaxf(mx, __shfl_xor_sync(0xffffffffu, mx, o));
        float xv = (hl < 10) ? expf(e - mx) : 0.f;
        float sv = xv;
#pragma unroll
        for (int o = 8; o; o >>= 1)
            sv += __shfl_xor_sync(0xffffffffu, sv, o);
        if (hl < 10) {
            const float al = xv / (sv + 1e-16f);
            g_alpha[d * 20 + head * 10 + hl] = al;
            atomicAdd(&g_w[s * 2 + head], al);
        }
    }
}

// ---------------- K4: emb[b] = (1/576) * sum_n w[n]*h[n] ----------------
__global__ void __launch_bounds__(256)
k_emb() {
    const int b = blockIdx.x;
    const int seg = blockIdx.y;       // 0..3, 144 rows each
    const int c = threadIdx.x;
    const int head = c >> 7;
    const int n0 = b * PN + seg * 144;
    float sum = 0.f;
#pragma unroll 4
    for (int p = 0; p < 144; p++) {
        int n = n0 + p;
        sum += g_w[n * 2 + head] * __half2float(g_h[(size_t)n * CH + c]);
    }
    atomicAdd(&g_emb[b * CH + c], sum * (1.0f / 576.0f));
}

// ---------------- K5: view GAT linear + logits ----------------
__global__ void __launch_bounds__(256)
k_gemm_view(const float* __restrict__ Wv, const float* __restrict__ asv,
            const float* __restrict__ adv, const float* __restrict__ bsp) {
    const int i = blockIdx.x;
    const int tid = threadIdx.x;
    __shared__ float se[256];
    __shared__ float r1[256], r2[256];
    se[tid] = g_emb[(i & 63) * CH + tid] + bsp[tid];
    __syncthreads();
    float acc = 0.f;
#pragma unroll 8
    for (int c = 0; c < 256; c++) acc += se[c] * Wv[c * 256 + tid];
    g_h2[i * CH + tid] = acc;
    r1[tid] = acc * asv[tid];
    r2[tid] = acc * adv[tid];
    __syncthreads();
    for (int o = 128; o; o >>= 1) {
        if (tid < o) { r1[tid] += r1[tid + o]; r2[tid] += r2[tid + o]; }
        __syncthreads();
    }
    if (tid == 0) { g_as2[i] = r1[0]; g_ad2[i] = r2[0]; }
}

// ---------------- K6: view GAT attention ----------------
__global__ void __launch_bounds__(256)
k_view_att(const void* __restrict__ ei, int E2, const float* __restrict__ bias) {
    __shared__ int   s_src[64];
    __shared__ float s_al[64];
    __shared__ int   s_cnt;
    const int d = blockIdx.x, tid = threadIdx.x;
    const int m64 = g_m64v;
    if (tid == 0) s_cnt = 0;
    __syncthreads();
    for (int e = tid; e < E2; e += 256) {
        int dd = eread(ei, (long long)E2 + e, m64);
        if (dd == d) {
            int pos = atomicAdd(&s_cnt, 1);
            s_src[pos] = eread(ei, e, m64);
        }
    }
    __syncthreads();
    if (tid == 0) {
        int cnt = s_cnt;
        s_src[cnt] = d;
        cnt++;
        const float ad = g_ad2[d];
        float m = -1e30f;
        for (int j = 0; j < cnt; j++) {
            float e = g_as2[s_src[j]] + ad;
            e = e > 0.f ? e : 0.2f * e;
            s_al[j] = e;
            m = fmaxf(m, e);
        }
        float sum = 0.f;
        for (int j = 0; j < cnt; j++) {
            float xx = expf(s_al[j] - m);
            s_al[j] = xx;
            sum += xx;
        }
        float inv = 1.f / (sum + 1e-16f);
        for (int j = 0; j < cnt; j++) s_al[j] *= inv;
        s_cnt = cnt;
    }
    __syncthreads();
    const int cnt = s_cnt;
    float acc = 0.f;
    for (int j = 0; j < cnt; j++) acc += s_al[j] * g_h2[s_src[j] * CH + tid];
    g_feat[d * CH + tid] = acc + bias[tid];
}

// ---------------- K7: final gather + blend (write-only out) ----------------
// Half-warp per head; alpha precomputed. out = 0.5*(sum a*h + bias) + 0.5*feat[img].
__global__ void __launch_bounds__(256, 5)
k_aggf(const void* __restrict__ ei, const float* __restrict__ bias,
       float* __restrict__ out) {
    const int tid = threadIdx.x, warp = tid >> 5, lane = tid & 31;
    const int hl = lane & 15;
    const int hsel = lane & 16;
    const int head = lane >> 4;
    const int img = blockIdx.x / 18;
    const int sec = blockIdx.x - img * 18;
    const int d0 = img * PN + sec * 32 + warp * 4;
    const int m64 = g_m64s;
    const int c0 = lane * 8;

    float cb[8];     // 0.5*bias + 0.5*feat (constant per lane per image)
    {
        float bbv[8], ffv[8];
        *(float4*)(bbv)     = *(const float4*)&bias[c0];
        *(float4*)(bbv + 4) = *(const float4*)&bias[c0 + 4];
        *(float4*)(ffv)     = *(const float4*)&g_feat[img * CH + c0];
        *(float4*)(ffv + 4) = *(const float4*)&g_feat[img * CH + c0 + 4];
#pragma unroll
        for (int i = 0; i < 8; i++) cb[i] = 0.5f * (bbv[i] + ffv[i]);
    }

#pragma unroll
    for (int r = 0; r < 4; r++) {
        const int d = d0 + r;

        int s = d;
        if (hl < 9) s = eread(ei, (long long)d * KNN + hl, m64);
        float al = 0.f;
        if (hl < 10) al = g_alpha[d * 20 + head * 10 + hl];

        float acc[8];
#pragma unroll
        for (int i = 0; i < 8; i++) acc[i] = 0.f;
#pragma unroll
        for (int j = 0; j < 10; j++) {
            const int idx = hsel + j;
            const int   sj = __shfl_sync(0xffffffffu, s,  idx);
            const float w  = __shfl_sync(0xffffffffu, al, idx);
            uint4 raw = *(const uint4*)&g_h[(size_t)sj * CH + c0];
            float2 f0 = __half22float2(*(__half2*)&raw.x);
            float2 f1 = __half22float2(*(__half2*)&raw.y);
            float2 f2 = __half22float2(*(__half2*)&raw.z);
            float2 f3 = __half22float2(*(__half2*)&raw.w);
            acc[0] += w * f0.x; acc[1] += w * f0.y;
            acc[2] += w * f1.x; acc[3] += w * f1.y;
            acc[4] += w * f2.x; acc[5] += w * f2.y;
            acc[6] += w * f3.x; acc[7] += w * f3.y;
        }

        float4 o0 = make_float4(0.5f * acc[0] + cb[0], 0.5f * acc[1] + cb[1],
                                0.5f * acc[2] + cb[2], 0.5f * acc[3] + cb[3]);
        float4 o1 = make_float4(0.5f * acc[4] + cb[4], 0.5f * acc[5] + cb[5],
                                0.5f * acc[6] + cb[6], 0.5f * acc[7] + cb[7]);
        *(float4*)&out[(size_t)d * CH + c0]     = o0;
        *(float4*)&out[(size_t)d * CH + c0 + 4] = o1;
    }
}

// ---------------- launch ----------------
extern "C" void kernel_launch(void* const* d_in, const int* in_sizes, int n_in,
                              void* d_out, int out_size) {
    const float* x    = (const float*)d_in[0];
    const void*  ei_s = d_in[3];
    const void*  ei_v = d_in[4];
    const float* Wsp  = (const float*)d_in[5];
    const float* asrc = (const float*)d_in[6];
    const float* adst = (const float*)d_in[7];
    const float* bsp  = (const float*)d_in[8];
    const float* Wv   = (const float*)d_in[9];
    const float* asv  = (const float*)d_in[10];
    const float* adv  = (const float*)d_in[11];
    const float* bv   = (const float*)d_in[12];
    float* out = (float*)d_out;

    const int E2 = in_sizes[4] / 2;

    cudaFuncSetAttribute(k_gemm_mma, cudaFuncAttributeMaxDynamicSharedMemorySize, SM_TOTAL);

    k_detect<<<1, 32>>>((const unsigned int*)ei_s, (const unsigned int*)ei_v, E2);
    k_prep<<<288, 256>>>(Wsp);
    k_gemm_mma<<<288, 512, SM_TOTAL>>>(x, asrc, adst);   // idx 2
    k_alpha<<<1152, 256>>>(ei_s);                        // idx 3 -> profiled
    k_emb<<<dim3(64, 4), 256>>>();
    k_gemm_view<<<128, 256>>>(Wv, asv, adv, bsp);
    k_view_att<<<128, 256>>>(ei_v, E2, bv);
    k_aggf<<<1152, 256>>>(ei_s, bsp, out);
}

// round 13
// speedup vs baseline: 1.0205x; 1.0205x over previous
#include <cuda_runtime.h>
#include <cuda_fp16.h>
#include <stdint.h>

// ---------------- problem constants ----------------
#define PN      576
#define B0c     64
#define BTOT    128
#define CIN     256
#define CH      256
#define NNODES  36864
#define KNN     9

// ---------------- scratch (device globals) ----------------
__device__ __align__(16) __half g_h  [NNODES * CH];   // GEMM output, fp16
__device__ __align__(16) __half g_xs [NNODES * CH];   // 0.5*(agg+bias), fp16 scratch
__device__ float g_as [NNODES * 2];
__device__ float g_ad [NNODES * 2];
__device__ __align__(16) float g_emb [B0c * CH];
__device__ __align__(16) float g_h2  [BTOT * CH];
__device__ float g_as2[BTOT];
__device__ float g_ad2[BTOT];
__device__ __align__(16) float g_feat[BTOT * CH];
__device__ int   g_m64s;
__device__ int   g_m64v;
// pre-converted, pre-swizzled W_space as B operand: [chunk][n=256][kk=64] fp16, SW128 rows
__device__ __align__(16) __half g_Bhi[4 * 256 * 64];
__device__ __align__(16) __half g_Blo[4 * 256 * 64];

// ---------------- helpers ----------------
__device__ __forceinline__ uint32_t smem_u32(const void* p) {
    return (uint32_t)__cvta_generic_to_shared(p);
}
__device__ __forceinline__ uint32_t sw128(uint32_t bo) { return bo ^ ((bo >> 3) & 0x70); }

__device__ __forceinline__ void cp_async16(uint32_t s, const void* g) {
    asm volatile("{\n\t.reg .u64 p;\n\tcvta.to.global.u64 p, %1;\n\t"
                 "cp.async.cg.shared.global [%0], [p], 16;\n\t}"
                 :: "r"(s), "l"(g) : "memory");
}
__device__ __forceinline__ void cp_commit() {
    asm volatile("cp.async.commit_group;" ::: "memory");
}
__device__ __forceinline__ void cp_wait0() {
    asm volatile("cp.async.wait_group 0;" ::: "memory");
}
__device__ __forceinline__ void ldmx4(uint32_t* r, uint32_t addr) {
    asm volatile("ldmatrix.sync.aligned.m8n8.x4.shared.b16 {%0,%1,%2,%3}, [%4];"
                 : "=r"(r[0]), "=r"(r[1]), "=r"(r[2]), "=r"(r[3]) : "r"(addr));
}
__device__ __forceinline__ void mma16816(float* d, const uint32_t* a,
                                         uint32_t b0, uint32_t b1) {
    asm volatile("mma.sync.aligned.m16n8k16.row.col.f32.f16.f16.f32 "
                 "{%0,%1,%2,%3}, {%4,%5,%6,%7}, {%8,%9}, {%0,%1,%2,%3};"
                 : "+f"(d[0]), "+f"(d[1]), "+f"(d[2]), "+f"(d[3])
                 : "r"(a[0]), "r"(a[1]), "r"(a[2]), "r"(a[3]), "r"(b0), "r"(b1));
}

// edge index read robust to int32/int64 storage
__device__ __forceinline__ int eread(const void* p, long long i, int m64) {
    if (m64) return (int)((const long long*)p)[i];
    return ((const int*)p)[i];
}

// ---------------- K0: dtype detection ----------------
__global__ void k_detect(const unsigned int* __restrict__ es,
                         const unsigned int* __restrict__ ev, int nv) {
    if (threadIdx.x == 0) {
        int nz = 0;
        for (int i = 0; i < 64; i++) nz += (es[2 * i + 1] != 0u);
        g_m64s = (nz == 0) ? 1 : 0;
        nz = 0;
        int m = nv < 64 ? nv : 64;
        for (int i = 0; i < m; i++) nz += (ev[2 * i + 1] != 0u);
        g_m64v = (nz == 0) ? 1 : 0;
    }
}

// ---------------- K1: prep W (swizzled fp16 hi/lo) ----------------
__global__ void __launch_bounds__(256) k_prep(const float* __restrict__ W) {
    int idx = blockIdx.x * 256 + threadIdx.x;   // 0..65535
    int chunk = idx >> 14;
    int r = idx & 16383;
    int n = r >> 6;
    int kk = r & 63;
    int c = chunk * 64 + kk;
    float v = W[c * 256 + n];
    __half hi = __float2half(v);
    __half lo = __float2half(v - __half2float(hi));
    uint32_t sw = sw128((uint32_t)n * 128 + kk * 2);
    *(__half*)((char*)g_Bhi + chunk * 32768 + sw) = hi;
    *(__half*)((char*)g_Blo + chunk * 32768 + sw) = lo;
}

// ---------------- K1b: zero emb (separate launch so GEMM is 4th = profiled) ------
__global__ void k_zero() {
    int idx = blockIdx.x * 256 + threadIdx.x;
    if (idx < B0c * CH) g_emb[idx] = 0.f;
}

// ---------------- K2: 2-term fp16 mma.sync GEMM + fused attention logits ----------
#define BUFSZ    81920
#define OFF_BHI  16384
#define OFF_BLO  49152
#define OFF_VAS  (2 * BUFSZ)
#define OFF_VAD  (2 * BUFSZ + 1024)
#define OFF_PAS  (2 * BUFSZ + 2048)
#define OFF_PAD  (2 * BUFSZ + 3072)
#define SM_TOTAL (2 * BUFSZ + 4096 + 1024)

__global__ void __launch_bounds__(512)
k_gemm_mma(const float* __restrict__ x, const float* __restrict__ asrc,
           const float* __restrict__ adst) {
    extern __shared__ char dsm[];
    const uint32_t sb_raw = smem_u32(dsm);
    const uint32_t pad = ((sb_raw + 1023u) & ~1023u) - sb_raw;
    char* base = dsm + pad;
    const uint32_t sb = sb_raw + pad;

    const int tid = threadIdx.x;
    const int wid = tid >> 5, lane = tid & 31;
    float* s_vas = (float*)(base + OFF_VAS);
    float* s_vad = (float*)(base + OFF_VAD);
    float* s_pas = (float*)(base + OFF_PAS);
    float* s_pad = (float*)(base + OFF_PAD);
    if (tid < 256) {
        s_vas[tid] = asrc[tid];
        s_vad[tid] = adst[tid];
        s_pas[tid] = 0.f;
        s_pad[tid] = 0.f;
    }

    const int tile_m = blockIdx.x * 128;
    const int ml = tid & 127;
    const int q  = tid >> 7;
    const int m = tile_m + ml;
    const unsigned bimg = (unsigned)m / 576u;
    const unsigned p = (unsigned)m - bimg * 576u;
    const float* xb = x + (size_t)bimg * (CIN * PN) + p;

    // ---- prologue: chunk 0 into buf 0
    {
        const char* sH = (const char*)g_Bhi;
        const char* sL = (const char*)g_Blo;
#pragma unroll
        for (int i = 0; i < 4; i++) {
            cp_async16(sb + OFF_BHI + tid * 16 + i * 8192, sH + tid * 16 + i * 8192);
            cp_async16(sb + OFF_BLO + tid * 16 + i * 8192, sL + tid * 16 + i * 8192);
        }
        cp_commit();
        char* Ah = base;
#pragma unroll
        for (int s = 0; s < 8; s++) {
            int kp = s * 4 + q;
            float v0 = xb[(size_t)(kp * 2) * PN];
            float v1 = xb[(size_t)(kp * 2 + 1) * PN];
            __half2 hh; hh.x = __float2half(v0); hh.y = __float2half(v1);
            uint32_t sw = sw128((uint32_t)ml * 128 + kp * 4);
            *(__half2*)(Ah + sw) = hh;
        }
        cp_wait0();
    }
    __syncthreads();

    // ---- main loop
    const int wm = wid & 3, wn = wid >> 2;
    const int mi = lane >> 3, rr = lane & 7;
    float d[2][8][4];
#pragma unroll
    for (int a = 0; a < 2; a++)
#pragma unroll
        for (int b = 0; b < 8; b++)
#pragma unroll
            for (int c = 0; c < 4; c++) d[a][b][c] = 0.f;

    float va[16];
    for (int c = 0; c < 4; c++) {
        const int buf = c & 1;
        const uint32_t Ab = sb + buf * BUFSZ;
        const uint32_t Bb = Ab + OFF_BHI;

        if (c < 3) {
            const uint32_t Ab2 = sb + (buf ^ 1) * BUFSZ;
            const char* sH = (const char*)g_Bhi + (c + 1) * 32768;
            const char* sL = (const char*)g_Blo + (c + 1) * 32768;
#pragma unroll
            for (int i = 0; i < 4; i++) {
                cp_async16(Ab2 + OFF_BHI + tid * 16 + i * 8192, sH + tid * 16 + i * 8192);
                cp_async16(Ab2 + OFF_BLO + tid * 16 + i * 8192, sL + tid * 16 + i * 8192);
            }
            cp_commit();
            const float* xc = xb + (size_t)(c + 1) * 64 * PN;
#pragma unroll
            for (int s = 0; s < 8; s++) {
                int kp = s * 4 + q;
                va[s * 2]     = xc[(size_t)(kp * 2) * PN];
                va[s * 2 + 1] = xc[(size_t)(kp * 2 + 1) * PN];
            }
        }

#pragma unroll
        for (int ks = 0; ks < 4; ks++) {
            const int kb = ks * 32;
            uint32_t ah[2][4];
#pragma unroll
            for (int mt = 0; mt < 2; mt++) {
                uint32_t aoff = sw128((uint32_t)(wm * 32 + mt * 16 + (mi & 1) * 8 + rr) * 128
                                      + kb + (mi >> 1) * 16);
                ldmx4(ah[mt], Ab + aoff);
            }
#pragma unroll
            for (int bt = 0; bt < 4; bt++) {
                uint32_t boff = sw128((uint32_t)(wn * 64 + bt * 16 + (mi >> 1) * 8 + rr) * 128
                                      + kb + (mi & 1) * 16);
                uint32_t bhi[4], blo[4];
                ldmx4(bhi, Bb + boff);
                ldmx4(blo, Bb + (OFF_BLO - OFF_BHI) + boff);
#pragma unroll
                for (int mt = 0; mt < 2; mt++)
#pragma unroll
                    for (int sub = 0; sub < 2; sub++)
                        mma16816(d[mt][bt * 2 + sub], ah[mt], bhi[sub * 2], bhi[sub * 2 + 1]);
#pragma unroll
                for (int mt = 0; mt < 2; mt++)
#pragma unroll
                    for (int sub = 0; sub < 2; sub++)
                        mma16816(d[mt][bt * 2 + sub], ah[mt], blo[sub * 2], blo[sub * 2 + 1]);
            }
        }

        if (c < 3) {
            char* Ah = base + (buf ^ 1) * BUFSZ;
#pragma unroll
            for (int s = 0; s < 8; s++) {
                int kp = s * 4 + q;
                __half2 hh; hh.x = __float2half(va[s * 2]); hh.y = __float2half(va[s * 2 + 1]);
                uint32_t sw = sw128((uint32_t)ml * 128 + kp * 4);
                *(__half2*)(Ah + sw) = hh;
            }
            cp_wait0();
            __syncthreads();
        }
    }

    // ---- epilogue: store g_h (fp16) + fused logits from fp32 accumulators
    float ps[2][2], pd[2][2];
#pragma unroll
    for (int a = 0; a < 2; a++) { ps[a][0] = ps[a][1] = pd[a][0] = pd[a][1] = 0.f; }

    const int g = lane >> 2, t4 = lane & 3;
#pragma unroll
    for (int mt = 0; mt < 2; mt++) {
        const int rg = tile_m + wm * 32 + mt * 16 + g;
#pragma unroll
        for (int bt = 0; bt < 4; bt++) {
#pragma unroll
            for (int sub = 0; sub < 2; sub++) {
                const int col = wn * 64 + bt * 16 + sub * 8 + t4 * 2;
                const float* dd = d[mt][bt * 2 + sub];
                float a0 = s_vas[col], a1 = s_vas[col + 1];
                float b0 = s_vad[col], b1 = s_vad[col + 1];
                ps[mt][0] += dd[0] * a0 + dd[1] * a1;
                pd[mt][0] += dd[0] * b0 + dd[1] * b1;
                ps[mt][1] += dd[2] * a0 + dd[3] * a1;
                pd[mt][1] += dd[2] * b0 + dd[3] * b1;
                __half2 h0; h0.x = __float2half(dd[0]); h0.y = __float2half(dd[1]);
                __half2 h1; h1.x = __float2half(dd[2]); h1.y = __float2half(dd[3]);
                *(__half2*)&g_h[(size_t)rg * CH + col]       = h0;
                *(__half2*)&g_h[(size_t)(rg + 8) * CH + col] = h1;
            }
        }
    }
#pragma unroll
    for (int mt = 0; mt < 2; mt++) {
#pragma unroll
        for (int hh = 0; hh < 2; hh++) {
            ps[mt][hh] += __shfl_xor_sync(0xffffffffu, ps[mt][hh], 1);
            ps[mt][hh] += __shfl_xor_sync(0xffffffffu, ps[mt][hh], 2);
            pd[mt][hh] += __shfl_xor_sync(0xffffffffu, pd[mt][hh], 1);
            pd[mt][hh] += __shfl_xor_sync(0xffffffffu, pd[mt][hh], 2);
        }
    }
    if (t4 == 0) {
        const int head = wn >> 1;
#pragma unroll
        for (int mt = 0; mt < 2; mt++) {
            const int rl = wm * 32 + mt * 16 + g;
            atomicAdd(&s_pas[rl * 2 + head],       ps[mt][0]);
            atomicAdd(&s_pad[rl * 2 + head],       pd[mt][0]);
            atomicAdd(&s_pas[(rl + 8) * 2 + head], ps[mt][1]);
            atomicAdd(&s_pad[(rl + 8) * 2 + head], pd[mt][1]);
        }
    }
    __syncthreads();
    if (tid < 256) {
        g_as[tile_m * 2 + tid] = s_pas[tid];
        g_ad[tile_m * 2 + tid] = s_pad[tid];
    }
}

// ---------------- K3: fused softmax + gather(fp16) -> g_xs(fp16) + image pooling ----
// Half-warp per head: lanes 0-15 head0, lanes 16-31 head1.
__global__ void __launch_bounds__(256, 5)
k_aggc(const void* __restrict__ ei, const float* __restrict__ bias) {
    __shared__ float sm[8][256];
    const int tid = threadIdx.x, warp = tid >> 5, lane = tid & 31;
    const int hl = lane & 15;
    const int hsel = lane & 16;
    const int head = lane >> 4;
    const int img = blockIdx.x / 18;
    const int sec = blockIdx.x - img * 18;
    const int d0 = img * PN + sec * 32 + warp * 4;
    const int m64 = g_m64s;
    const int c0 = lane * 8;

    float bb[8];
    *(float4*)(bb)     = *(const float4*)&bias[c0];
    *(float4*)(bb + 4) = *(const float4*)&bias[c0 + 4];

    float embp[8];
#pragma unroll
    for (int i = 0; i < 8; i++) embp[i] = 0.f;

#pragma unroll
    for (int r = 0; r < 4; r++) {
        const int d = d0 + r;

        int s = d;
        if (hl < 9) s = eread(ei, (long long)d * KNN + hl, m64);

        float e = -1e30f;
        if (hl < 10) {
            e = g_as[s * 2 + head] + g_ad[d * 2 + head];
            e = e > 0.f ? e : 0.2f * e;
        }
        float mx = e;
#pragma unroll
        for (int o = 8; o; o >>= 1)
            mx = fmaxf(mx, __shfl_xor_sync(0xffffffffu, mx, o));
        float xv = (hl < 10) ? expf(e - mx) : 0.f;
        float sv = xv;
#pragma unroll
        for (int o = 8; o; o >>= 1)
            sv += __shfl_xor_sync(0xffffffffu, sv, o);
        const float al = xv / (sv + 1e-16f);

        float acc[8];
#pragma unroll
        for (int i = 0; i < 8; i++) acc[i] = 0.f;
#pragma unroll
        for (int j = 0; j < 10; j++) {
            const int idx = hsel + j;
            const int   sj = __shfl_sync(0xffffffffu, s,  idx);
            const float w  = __shfl_sync(0xffffffffu, al, idx);
            uint4 raw = *(const uint4*)&g_h[(size_t)sj * CH + c0];
            float2 f0 = __half22float2(*(__half2*)&raw.x);
            float2 f1 = __half22float2(*(__half2*)&raw.y);
            float2 f2 = __half22float2(*(__half2*)&raw.z);
            float2 f3 = __half22float2(*(__half2*)&raw.w);
            acc[0] += w * f0.x; acc[1] += w * f0.y;
            acc[2] += w * f1.x; acc[3] += w * f1.y;
            acc[4] += w * f2.x; acc[5] += w * f2.y;
            acc[6] += w * f3.x; acc[7] += w * f3.y;
        }

#pragma unroll
        for (int i = 0; i < 8; i++) embp[i] += acc[i];

        // fp16 scratch: 0.5*(acc + bias)
        __half2 q0 = __floats2half2_rn(0.5f * (acc[0] + bb[0]), 0.5f * (acc[1] + bb[1]));
        __half2 q1 = __floats2half2_rn(0.5f * (acc[2] + bb[2]), 0.5f * (acc[3] + bb[3]));
        __half2 q2 = __floats2half2_rn(0.5f * (acc[4] + bb[4]), 0.5f * (acc[5] + bb[5]));
        __half2 q3 = __floats2half2_rn(0.5f * (acc[6] + bb[6]), 0.5f * (acc[7] + bb[7]));
        uint4 wv;
        wv.x = *(uint32_t*)&q0; wv.y = *(uint32_t*)&q1;
        wv.z = *(uint32_t*)&q2; wv.w = *(uint32_t*)&q3;
        *(uint4*)&g_xs[(size_t)d * CH + c0] = wv;
    }

    // block pool
#pragma unroll
    for (int i = 0; i < 8; i++) sm[warp][c0 + i] = embp[i];
    __syncthreads();
    float sum = 0.f;
#pragma unroll
    for (int w = 0; w < 8; w++) sum += sm[w][tid];
    atomicAdd(&g_emb[img * CH + tid], sum);
}

// ---------------- K4: view GAT linear + logits ----------------
__global__ void __launch_bounds__(256)
k_gemm_view(const float* __restrict__ Wv, const float* __restrict__ asv,
            const float* __restrict__ adv, const float* __restrict__ bsp) {
    const int i = blockIdx.x;
    const int tid = threadIdx.x;
    __shared__ float se[256];
    __shared__ float r1[256], r2[256];
    se[tid] = g_emb[(i & 63) * CH + tid] * (1.0f / 576.0f) + bsp[tid];
    __syncthreads();
    float acc = 0.f;
#pragma unroll 8
    for (int c = 0; c < 256; c++) acc += se[c] * Wv[c * 256 + tid];
    g_h2[i * CH + tid] = acc;
    r1[tid] = acc * asv[tid];
    r2[tid] = acc * adv[tid];
    __syncthreads();
    for (int o = 128; o; o >>= 1) {
        if (tid < o) { r1[tid] += r1[tid + o]; r2[tid] += r2[tid + o]; }
        __syncthreads();
    }
    if (tid == 0) { g_as2[i] = r1[0]; g_ad2[i] = r2[0]; }
}

// ---------------- K5: view GAT attention ----------------
__global__ void __launch_bounds__(256)
k_view_att(const void* __restrict__ ei, int E2, const float* __restrict__ bias) {
    __shared__ int   s_src[64];
    __shared__ float s_al[64];
    __shared__ int   s_cnt;
    const int d = blockIdx.x, tid = threadIdx.x;
    const int m64 = g_m64v;
    if (tid == 0) s_cnt = 0;
    __syncthreads();
    for (int e = tid; e < E2; e += 256) {
        int dd = eread(ei, (long long)E2 + e, m64);
        if (dd == d) {
            int pos = atomicAdd(&s_cnt, 1);
            s_src[pos] = eread(ei, e, m64);
        }
    }
    __syncthreads();
    if (tid == 0) {
        int cnt = s_cnt;
        s_src[cnt] = d;
        cnt++;
        const float ad = g_ad2[d];
        float m = -1e30f;
        for (int j = 0; j < cnt; j++) {
            float e = g_as2[s_src[j]] + ad;
            e = e > 0.f ? e : 0.2f * e;
            s_al[j] = e;
            m = fmaxf(m, e);
        }
        float sum = 0.f;
        for (int j = 0; j < cnt; j++) {
            float xx = expf(s_al[j] - m);
            s_al[j] = xx;
            sum += xx;
        }
        float inv = 1.f / (sum + 1e-16f);
        for (int j = 0; j < cnt; j++) s_al[j] *= inv;
        s_cnt = cnt;
    }
    __syncthreads();
    const int cnt = s_cnt;
    float acc = 0.f;
    for (int j = 0; j < cnt; j++) acc += s_al[j] * g_h2[s_src[j] * CH + tid];
    g_feat[d * CH + tid] = acc + bias[tid];
}

// ---------------- K6: out = g_xs + 0.5*feat[b]  (fp16 read, fp32 write) ----------
__global__ void __launch_bounds__(256)
k_blend(float* __restrict__ out) {
    const int g = blockIdx.x * 256 + threadIdx.x;   // 8-channel group index
    const unsigned row = (unsigned)g >> 5;           // 32 groups per row
    const int c0 = (g & 31) * 8;
    const unsigned b = row / 576u;

    uint4 raw = *(const uint4*)&g_xs[(size_t)row * CH + c0];
    float2 f0 = __half22float2(*(__half2*)&raw.x);
    float2 f1 = __half22float2(*(__half2*)&raw.y);
    float2 f2 = __half22float2(*(__half2*)&raw.z);
    float2 f3 = __half22float2(*(__half2*)&raw.w);

    float4 ft0 = *(const float4*)&g_feat[b * CH + c0];
    float4 ft1 = *(const float4*)&g_feat[b * CH + c0 + 4];

    float4 o0 = make_float4(f0.x + 0.5f * ft0.x, f0.y + 0.5f * ft0.y,
                            f1.x + 0.5f * ft0.z, f1.y + 0.5f * ft0.w);
    float4 o1 = make_float4(f2.x + 0.5f * ft1.x, f2.y + 0.5f * ft1.y,
                            f3.x + 0.5f * ft1.z, f3.y + 0.5f * ft1.w);
    *(float4*)&out[(size_t)row * CH + c0]     = o0;
    *(float4*)&out[(size_t)row * CH + c0 + 4] = o1;
}

// ---------------- launch ----------------
extern "C" void kernel_launch(void* const* d_in, const int* in_sizes, int n_in,
                              void* d_out, int out_size) {
    const float* x    = (const float*)d_in[0];
    const void*  ei_s = d_in[3];
    const void*  ei_v = d_in[4];
    const float* Wsp  = (const float*)d_in[5];
    const float* asrc = (const float*)d_in[6];
    const float* adst = (const float*)d_in[7];
    const float* bsp  = (const float*)d_in[8];
    const float* Wv   = (const float*)d_in[9];
    const float* asv  = (const float*)d_in[10];
    const float* adv  = (const float*)d_in[11];
    const float* bv   = (const float*)d_in[12];
    float* out = (float*)d_out;

    const int E2 = in_sizes[4] / 2;

    cudaFuncSetAttribute(k_gemm_mma, cudaFuncAttributeMaxDynamicSharedMemorySize, SM_TOTAL);

    k_detect<<<1, 32>>>((const unsigned int*)ei_s, (const unsigned int*)ei_v, E2);
    k_prep<<<256, 256>>>(Wsp);
    k_zero<<<64, 256>>>();
    k_gemm_mma<<<288, 512, SM_TOTAL>>>(x, asrc, adst);   // 4th launch -> profiled
    k_aggc<<<1152, 256>>>(ei_s, bsp);
    k_gemm_view<<<128, 256>>>(Wv, asv, adv, bsp);
    k_view_att<<<128, 256>>>(ei_v, E2, bv);
    k_blend<<<NNODES * CH / 8 / 256, 256>>>(out);
}

// round 14
// speedup vs baseline: 1.1218x; 1.0992x over previous
#include <cuda_runtime.h>
#include <cuda_fp16.h>
#include <stdint.h>

// ---------------- problem constants ----------------
#define PN      576
#define B0c     64
#define BTOT    128
#define CIN     256
#define CH      256
#define NNODES  36864
#define KNN     9

// ---------------- scratch (device globals) ----------------
__device__ __align__(16) __half g_h  [NNODES * CH];   // GEMM output, fp16
__device__ __align__(16) __half g_xs [NNODES * CH];   // 0.5*(agg+bias), fp16 scratch
__device__ float g_as [NNODES * 2];
__device__ float g_ad [NNODES * 2];
__device__ __align__(16) float g_emb [B0c * CH];
__device__ __align__(16) float g_h2  [BTOT * CH];
__device__ float g_as2[BTOT];
__device__ float g_ad2[BTOT];
__device__ __align__(16) float g_feat[BTOT * CH];
__device__ int   g_m64s;
__device__ int   g_m64v;
// pre-converted, pre-swizzled W_space as B operand: [chunk][n=256][kk=64] fp16, SW128 rows
__device__ __align__(16) __half g_Bhi[4 * 256 * 64];

// ---------------- helpers ----------------
__device__ __forceinline__ uint32_t smem_u32(const void* p) {
    return (uint32_t)__cvta_generic_to_shared(p);
}
__device__ __forceinline__ uint32_t sw128(uint32_t bo) { return bo ^ ((bo >> 3) & 0x70); }

__device__ __forceinline__ void cp_async16(uint32_t s, const void* g) {
    asm volatile("{\n\t.reg .u64 p;\n\tcvta.to.global.u64 p, %1;\n\t"
                 "cp.async.cg.shared.global [%0], [p], 16;\n\t}"
                 :: "r"(s), "l"(g) : "memory");
}
__device__ __forceinline__ void cp_commit() {
    asm volatile("cp.async.commit_group;" ::: "memory");
}
__device__ __forceinline__ void cp_wait0() {
    asm volatile("cp.async.wait_group 0;" ::: "memory");
}
__device__ __forceinline__ void ldmx4(uint32_t* r, uint32_t addr) {
    asm volatile("ldmatrix.sync.aligned.m8n8.x4.shared.b16 {%0,%1,%2,%3}, [%4];"
                 : "=r"(r[0]), "=r"(r[1]), "=r"(r[2]), "=r"(r[3]) : "r"(addr));
}
__device__ __forceinline__ void mma16816(float* d, const uint32_t* a,
                                         uint32_t b0, uint32_t b1) {
    asm volatile("mma.sync.aligned.m16n8k16.row.col.f32.f16.f16.f32 "
                 "{%0,%1,%2,%3}, {%4,%5,%6,%7}, {%8,%9}, {%0,%1,%2,%3};"
                 : "+f"(d[0]), "+f"(d[1]), "+f"(d[2]), "+f"(d[3])
                 : "r"(a[0]), "r"(a[1]), "r"(a[2]), "r"(a[3]), "r"(b0), "r"(b1));
}

// edge index read robust to int32/int64 storage
__device__ __forceinline__ int eread(const void* p, long long i, int m64) {
    if (m64) return (int)((const long long*)p)[i];
    return ((const int*)p)[i];
}

// ---------------- K0: dtype detection ----------------
__global__ void k_detect(const unsigned int* __restrict__ es,
                         const unsigned int* __restrict__ ev, int nv) {
    if (threadIdx.x == 0) {
        int nz = 0;
        for (int i = 0; i < 64; i++) nz += (es[2 * i + 1] != 0u);
        g_m64s = (nz == 0) ? 1 : 0;
        nz = 0;
        int m = nv < 64 ? nv : 64;
        for (int i = 0; i < m; i++) nz += (ev[2 * i + 1] != 0u);
        g_m64v = (nz == 0) ? 1 : 0;
    }
}

// ---------------- K1: prep W (swizzled fp16) ----------------
__global__ void __launch_bounds__(256) k_prep(const float* __restrict__ W) {
    int idx = blockIdx.x * 256 + threadIdx.x;   // 0..65535
    int chunk = idx >> 14;
    int r = idx & 16383;
    int n = r >> 6;
    int kk = r & 63;
    int c = chunk * 64 + kk;
    float v = W[c * 256 + n];
    uint32_t sw = sw128((uint32_t)n * 128 + kk * 2);
    *(__half*)((char*)g_Bhi + chunk * 32768 + sw) = __float2half(v);
}

// ---------------- K1b: zero emb ----------------
__global__ void k_zero() {
    int idx = blockIdx.x * 256 + threadIdx.x;
    if (idx < B0c * CH) g_emb[idx] = 0.f;
}

// ---------------- K2: single-term fp16 mma.sync GEMM + fused attention logits ------
// 512 threads, 16 warps: wm = wid&3 (M 4x32), wn = wid>>2 (N 4x64). Warp tile 32x64.
#define BUFSZ    49152
#define OFF_BHI  16384
#define OFF_VAS  (2 * BUFSZ)
#define OFF_VAD  (2 * BUFSZ + 1024)
#define OFF_PAS  (2 * BUFSZ + 2048)
#define OFF_PAD  (2 * BUFSZ + 3072)
#define SM_TOTAL (2 * BUFSZ + 4096 + 1024)

__global__ void __launch_bounds__(512)
k_gemm_mma(const float* __restrict__ x, const float* __restrict__ asrc,
           const float* __restrict__ adst) {
    extern __shared__ char dsm[];
    const uint32_t sb_raw = smem_u32(dsm);
    const uint32_t pad = ((sb_raw + 1023u) & ~1023u) - sb_raw;
    char* base = dsm + pad;
    const uint32_t sb = sb_raw + pad;

    const int tid = threadIdx.x;
    const int wid = tid >> 5, lane = tid & 31;
    float* s_vas = (float*)(base + OFF_VAS);
    float* s_vad = (float*)(base + OFF_VAD);
    float* s_pas = (float*)(base + OFF_PAS);
    float* s_pad = (float*)(base + OFF_PAD);
    if (tid < 256) {
        s_vas[tid] = asrc[tid];
        s_vad[tid] = adst[tid];
        s_pas[tid] = 0.f;
        s_pad[tid] = 0.f;
    }

    const int tile_m = blockIdx.x * 128;
    const int ml = tid & 127;
    const int q  = tid >> 7;
    const int m = tile_m + ml;
    const unsigned bimg = (unsigned)m / 576u;
    const unsigned p = (unsigned)m - bimg * 576u;
    const float* xb = x + (size_t)bimg * (CIN * PN) + p;

    // ---- prologue: chunk 0 into buf 0
    {
        const char* sH = (const char*)g_Bhi;
#pragma unroll
        for (int i = 0; i < 4; i++)
            cp_async16(sb + OFF_BHI + tid * 16 + i * 8192, sH + tid * 16 + i * 8192);
        cp_commit();
        char* Ah = base;
#pragma unroll
        for (int s = 0; s < 8; s++) {
            int kp = s * 4 + q;
            float v0 = xb[(size_t)(kp * 2) * PN];
            float v1 = xb[(size_t)(kp * 2 + 1) * PN];
            __half2 hh; hh.x = __float2half(v0); hh.y = __float2half(v1);
            uint32_t sw = sw128((uint32_t)ml * 128 + kp * 4);
            *(__half2*)(Ah + sw) = hh;
        }
        cp_wait0();
    }
    __syncthreads();

    // ---- main loop
    const int wm = wid & 3, wn = wid >> 2;
    const int mi = lane >> 3, rr = lane & 7;
    float d[2][8][4];
#pragma unroll
    for (int a = 0; a < 2; a++)
#pragma unroll
        for (int b = 0; b < 8; b++)
#pragma unroll
            for (int c = 0; c < 4; c++) d[a][b][c] = 0.f;

    float va[16];
    for (int c = 0; c < 4; c++) {
        const int buf = c & 1;
        const uint32_t Ab = sb + buf * BUFSZ;
        const uint32_t Bb = Ab + OFF_BHI;

        if (c < 3) {
            const uint32_t Ab2 = sb + (buf ^ 1) * BUFSZ;
            const char* sH = (const char*)g_Bhi + (c + 1) * 32768;
#pragma unroll
            for (int i = 0; i < 4; i++)
                cp_async16(Ab2 + OFF_BHI + tid * 16 + i * 8192, sH + tid * 16 + i * 8192);
            cp_commit();
            const float* xc = xb + (size_t)(c + 1) * 64 * PN;
#pragma unroll
            for (int s = 0; s < 8; s++) {
                int kp = s * 4 + q;
                va[s * 2]     = xc[(size_t)(kp * 2) * PN];
                va[s * 2 + 1] = xc[(size_t)(kp * 2 + 1) * PN];
            }
        }

#pragma unroll
        for (int ks = 0; ks < 4; ks++) {
            const int kb = ks * 32;
            uint32_t ah[2][4];
#pragma unroll
            for (int mt = 0; mt < 2; mt++) {
                uint32_t aoff = sw128((uint32_t)(wm * 32 + mt * 16 + (mi & 1) * 8 + rr) * 128
                                      + kb + (mi >> 1) * 16);
                ldmx4(ah[mt], Ab + aoff);
            }
#pragma unroll
            for (int bt = 0; bt < 4; bt++) {
                uint32_t boff = sw128((uint32_t)(wn * 64 + bt * 16 + (mi >> 1) * 8 + rr) * 128
                                      + kb + (mi & 1) * 16);
                uint32_t bhi[4];
                ldmx4(bhi, Bb + boff);
#pragma unroll
                for (int mt = 0; mt < 2; mt++)
#pragma unroll
                    for (int sub = 0; sub < 2; sub++)
                        mma16816(d[mt][bt * 2 + sub], ah[mt], bhi[sub * 2], bhi[sub * 2 + 1]);
            }
        }

        if (c < 3) {
            char* Ah = base + (buf ^ 1) * BUFSZ;
#pragma unroll
            for (int s = 0; s < 8; s++) {
                int kp = s * 4 + q;
                __half2 hh; hh.x = __float2half(va[s * 2]); hh.y = __float2half(va[s * 2 + 1]);
                uint32_t sw = sw128((uint32_t)ml * 128 + kp * 4);
                *(__half2*)(Ah + sw) = hh;
            }
            cp_wait0();
            __syncthreads();
        }
    }

    // ---- epilogue: store g_h (fp16) + fused logits from fp32 accumulators
    float ps[2][2], pd[2][2];
#pragma unroll
    for (int a = 0; a < 2; a++) { ps[a][0] = ps[a][1] = pd[a][0] = pd[a][1] = 0.f; }

    const int g = lane >> 2, t4 = lane & 3;
#pragma unroll
    for (int mt = 0; mt < 2; mt++) {
        const int rg = tile_m + wm * 32 + mt * 16 + g;
#pragma unroll
        for (int bt = 0; bt < 4; bt++) {
#pragma unroll
            for (int sub = 0; sub < 2; sub++) {
                const int col = wn * 64 + bt * 16 + sub * 8 + t4 * 2;
                const float* dd = d[mt][bt * 2 + sub];
                float a0 = s_vas[col], a1 = s_vas[col + 1];
                float b0 = s_vad[col], b1 = s_vad[col + 1];
                ps[mt][0] += dd[0] * a0 + dd[1] * a1;
                pd[mt][0] += dd[0] * b0 + dd[1] * b1;
                ps[mt][1] += dd[2] * a0 + dd[3] * a1;
                pd[mt][1] += dd[2] * b0 + dd[3] * b1;
                __half2 h0; h0.x = __float2half(dd[0]); h0.y = __float2half(dd[1]);
                __half2 h1; h1.x = __float2half(dd[2]); h1.y = __float2half(dd[3]);
                *(__half2*)&g_h[(size_t)rg * CH + col]       = h0;
                *(__half2*)&g_h[(size_t)(rg + 8) * CH + col] = h1;
            }
        }
    }
#pragma unroll
    for (int mt = 0; mt < 2; mt++) {
#pragma unroll
        for (int hh = 0; hh < 2; hh++) {
            ps[mt][hh] += __shfl_xor_sync(0xffffffffu, ps[mt][hh], 1);
            ps[mt][hh] += __shfl_xor_sync(0xffffffffu, ps[mt][hh], 2);
            pd[mt][hh] += __shfl_xor_sync(0xffffffffu, pd[mt][hh], 1);
            pd[mt][hh] += __shfl_xor_sync(0xffffffffu, pd[mt][hh], 2);
        }
    }
    if (t4 == 0) {
        const int head = wn >> 1;
#pragma unroll
        for (int mt = 0; mt < 2; mt++) {
            const int rl = wm * 32 + mt * 16 + g;
            atomicAdd(&s_pas[rl * 2 + head],       ps[mt][0]);
            atomicAdd(&s_pad[rl * 2 + head],       pd[mt][0]);
            atomicAdd(&s_pas[(rl + 8) * 2 + head], ps[mt][1]);
            atomicAdd(&s_pad[(rl + 8) * 2 + head], pd[mt][1]);
        }
    }
    __syncthreads();
    if (tid < 256) {
        g_as[tile_m * 2 + tid] = s_pas[tid];
        g_ad[tile_m * 2 + tid] = s_pad[tid];
    }
}

// ---------------- K3: fused softmax + gather(fp16) -> g_xs(fp16) + image pooling ----
__global__ void __launch_bounds__(256, 5)
k_aggc(const void* __restrict__ ei, const float* __restrict__ bias) {
    __shared__ float sm[8][256];
    const int tid = threadIdx.x, warp = tid >> 5, lane = tid & 31;
    const int hl = lane & 15;
    const int hsel = lane & 16;
    const int head = lane >> 4;
    const int img = blockIdx.x / 18;
    const int sec = blockIdx.x - img * 18;
    const int d0 = img * PN + sec * 32 + warp * 4;
    const int m64 = g_m64s;
    const int c0 = lane * 8;

    float bb[8];
    *(float4*)(bb)     = *(const float4*)&bias[c0];
    *(float4*)(bb + 4) = *(const float4*)&bias[c0 + 4];

    float embp[8];
#pragma unroll
    for (int i = 0; i < 8; i++) embp[i] = 0.f;

#pragma unroll
    for (int r = 0; r < 4; r++) {
        const int d = d0 + r;

        int s = d;
        if (hl < 9) s = eread(ei, (long long)d * KNN + hl, m64);

        float e = -1e30f;
        if (hl < 10) {
            e = g_as[s * 2 + head] + g_ad[d * 2 + head];
            e = e > 0.f ? e : 0.2f * e;
        }
        float mx = e;
#pragma unroll
        for (int o = 8; o; o >>= 1)
            mx = fmaxf(mx, __shfl_xor_sync(0xffffffffu, mx, o));
        float xv = (hl < 10) ? expf(e - mx) : 0.f;
        float sv = xv;
#pragma unroll
        for (int o = 8; o; o >>= 1)
            sv += __shfl_xor_sync(0xffffffffu, sv, o);
        const float al = xv / (sv + 1e-16f);

        float acc[8];
#pragma unroll
        for (int i = 0; i < 8; i++) acc[i] = 0.f;
#pragma unroll
        for (int j = 0; j < 10; j++) {
            const int idx = hsel + j;
            const int   sj = __shfl_sync(0xffffffffu, s,  idx);
            const float w  = __shfl_sync(0xffffffffu, al, idx);
            uint4 raw = *(const uint4*)&g_h[(size_t)sj * CH + c0];
            float2 f0 = __half22float2(*(__half2*)&raw.x);
            float2 f1 = __half22float2(*(__half2*)&raw.y);
            float2 f2 = __half22float2(*(__half2*)&raw.z);
            float2 f3 = __half22float2(*(__half2*)&raw.w);
            acc[0] += w * f0.x; acc[1] += w * f0.y;
            acc[2] += w * f1.x; acc[3] += w * f1.y;
            acc[4] += w * f2.x; acc[5] += w * f2.y;
            acc[6] += w * f3.x; acc[7] += w * f3.y;
        }

#pragma unroll
        for (int i = 0; i < 8; i++) embp[i] += acc[i];

        __half2 q0 = __floats2half2_rn(0.5f * (acc[0] + bb[0]), 0.5f * (acc[1] + bb[1]));
        __half2 q1 = __floats2half2_rn(0.5f * (acc[2] + bb[2]), 0.5f * (acc[3] + bb[3]));
        __half2 q2 = __floats2half2_rn(0.5f * (acc[4] + bb[4]), 0.5f * (acc[5] + bb[5]));
        __half2 q3 = __floats2half2_rn(0.5f * (acc[6] + bb[6]), 0.5f * (acc[7] + bb[7]));
        uint4 wv;
        wv.x = *(uint32_t*)&q0; wv.y = *(uint32_t*)&q1;
        wv.z = *(uint32_t*)&q2; wv.w = *(uint32_t*)&q3;
        *(uint4*)&g_xs[(size_t)d * CH + c0] = wv;
    }

    // block pool
#pragma unroll
    for (int i = 0; i < 8; i++) sm[warp][c0 + i] = embp[i];
    __syncthreads();
    float sum = 0.f;
#pragma unroll
    for (int w = 0; w < 8; w++) sum += sm[w][tid];
    atomicAdd(&g_emb[img * CH + tid], sum);
}

// ---------------- K4: view GAT linear + logits ----------------
__global__ void __launch_bounds__(256)
k_gemm_view(const float* __restrict__ Wv, const float* __restrict__ asv,
            const float* __restrict__ adv, const float* __restrict__ bsp) {
    const int i = blockIdx.x;
    const int tid = threadIdx.x;
    __shared__ float se[256];
    __shared__ float r1[256], r2[256];
    se[tid] = g_emb[(i & 63) * CH + tid] * (1.0f / 576.0f) + bsp[tid];
    __syncthreads();
    float acc = 0.f;
#pragma unroll 8
    for (int c = 0; c < 256; c++) acc += se[c] * Wv[c * 256 + tid];
    g_h2[i * CH + tid] = acc;
    r1[tid] = acc * asv[tid];
    r2[tid] = acc * adv[tid];
    __syncthreads();
    for (int o = 128; o; o >>= 1) {
        if (tid < o) { r1[tid] += r1[tid + o]; r2[tid] += r2[tid + o]; }
        __syncthreads();
    }
    if (tid == 0) { g_as2[i] = r1[0]; g_ad2[i] = r2[0]; }
}

// ---------------- K5: view GAT attention ----------------
__global__ void __launch_bounds__(256)
k_view_att(const void* __restrict__ ei, int E2, const float* __restrict__ bias) {
    __shared__ int   s_src[64];
    __shared__ float s_al[64];
    __shared__ int   s_cnt;
    const int d = blockIdx.x, tid = threadIdx.x;
    const int m64 = g_m64v;
    if (tid == 0) s_cnt = 0;
    __syncthreads();
    for (int e = tid; e < E2; e += 256) {
        int dd = eread(ei, (long long)E2 + e, m64);
        if (dd == d) {
            int pos = atomicAdd(&s_cnt, 1);
            s_src[pos] = eread(ei, e, m64);
        }
    }
    __syncthreads();
    if (tid == 0) {
        int cnt = s_cnt;
        s_src[cnt] = d;
        cnt++;
        const float ad = g_ad2[d];
        float m = -1e30f;
        for (int j = 0; j < cnt; j++) {
            float e = g_as2[s_src[j]] + ad;
            e = e > 0.f ? e : 0.2f * e;
            s_al[j] = e;
            m = fmaxf(m, e);
        }
        float sum = 0.f;
        for (int j = 0; j < cnt; j++) {
            float xx = expf(s_al[j] - m);
            s_al[j] = xx;
            sum += xx;
        }
        float inv = 1.f / (sum + 1e-16f);
        for (int j = 0; j < cnt; j++) s_al[j] *= inv;
        s_cnt = cnt;
    }
    __syncthreads();
    const int cnt = s_cnt;
    float acc = 0.f;
    for (int j = 0; j < cnt; j++) acc += s_al[j] * g_h2[s_src[j] * CH + tid];
    g_feat[d * CH + tid] = acc + bias[tid];
}

// ---------------- K6: out = g_xs + 0.5*feat[b]  (fp16 read, fp32 write) ----------
__global__ void __launch_bounds__(256)
k_blend(float* __restrict__ out) {
    const int g = blockIdx.x * 256 + threadIdx.x;   // 8-channel group index
    const unsigned row = (unsigned)g >> 5;           // 32 groups per row
    const int c0 = (g & 31) * 8;
    const unsigned b = row / 576u;

    uint4 raw = *(const uint4*)&g_xs[(size_t)row * CH + c0];
    float2 f0 = __half22float2(*(__half2*)&raw.x);
    float2 f1 = __half22float2(*(__half2*)&raw.y);
    float2 f2 = __half22float2(*(__half2*)&raw.z);
    float2 f3 = __half22float2(*(__half2*)&raw.w);

    float4 ft0 = *(const float4*)&g_feat[b * CH + c0];
    float4 ft1 = *(const float4*)&g_feat[b * CH + c0 + 4];

    float4 o0 = make_float4(f0.x + 0.5f * ft0.x, f0.y + 0.5f * ft0.y,
                            f1.x + 0.5f * ft0.z, f1.y + 0.5f * ft0.w);
    float4 o1 = make_float4(f2.x + 0.5f * ft1.x, f2.y + 0.5f * ft1.y,
                            f3.x + 0.5f * ft1.z, f3.y + 0.5f * ft1.w);
    *(float4*)&out[(size_t)row * CH + c0]     = o0;
    *(float4*)&out[(size_t)row * CH + c0 + 4] = o1;
}

// ---------------- launch ----------------
extern "C" void kernel_launch(void* const* d_in, const int* in_sizes, int n_in,
                              void* d_out, int out_size) {
    const float* x    = (const float*)d_in[0];
    const void*  ei_s = d_in[3];
    const void*  ei_v = d_in[4];
    const float* Wsp  = (const float*)d_in[5];
    const float* asrc = (const float*)d_in[6];
    const float* adst = (const float*)d_in[7];
    const float* bsp  = (const float*)d_in[8];
    const float* Wv   = (const float*)d_in[9];
    const float* asv  = (const float*)d_in[10];
    const float* adv  = (const float*)d_in[11];
    const float* bv   = (const float*)d_in[12];
    float* out = (float*)d_out;

    const int E2 = in_sizes[4] / 2;

    cudaFuncSetAttribute(k_gemm_mma, cudaFuncAttributeMaxDynamicSharedMemorySize, SM_TOTAL);

    k_detect<<<1, 32>>>((const unsigned int*)ei_s, (const unsigned int*)ei_v, E2);
    k_prep<<<256, 256>>>(Wsp);
    k_zero<<<64, 256>>>();
    k_gemm_mma<<<288, 512, SM_TOTAL>>>(x, asrc, adst);   // 4th launch -> profiled
    k_aggc<<<1152, 256>>>(ei_s, bsp);
    k_gemm_view<<<128, 256>>>(Wv, asv, adv, bsp);
    k_view_att<<<128, 256>>>(ei_v, E2, bv);
    k_blend<<<NNODES * CH / 8 / 256, 256>>>(out);
}